// round 1
// baseline (speedup 1.0000x reference)
#include <cuda_runtime.h>
#include <math.h>

#define Bb 64
#define Nn 4096
#define Ff 128
#define Kk 64
#define NSTEP 4
#define SPLITS 16
#define TN 64
#define ROWS_PER_BLOCK (Nn / SPLITS)          // 256
#define TILES_PER_BLOCK (ROWS_PER_BLOCK / TN) // 4

// ---- scratch (static __device__, no allocations) ----
__device__ float g_x[(size_t)Bb * Nn * Ff];        // 128 MB normalized x
__device__ float g_sum[Bb * Ff];
__device__ float g_sumsq[Bb * Ff];
__device__ float g_mu[2][Bb * Kk * Ff];            // ping-pong mu buffers

// shared layout (floats) for k_em
#define SH_MU   0                      // [64][129]
#define SH_X    8256                   // [64][128]
#define SH_P    16448                  // [64][68]
#define SH_RED  20800                  // [64][17]
#define SH_ROW  21888                  // [64]
#define SH_X2   21952                  // [64]
#define SH_M2   22016                  // [64]
#define SH_TOTAL_FLOATS 22080
#define SH_BYTES (SH_TOTAL_FLOATS * 4) // 88320

__global__ void k_zero_stats() {
    int i = blockIdx.x * blockDim.x + threadIdx.x;
    if (i < Bb * Ff) { g_sum[i] = 0.f; g_sumsq[i] = 0.f; }
}

__global__ void k_zero_mu(int dst) {
    int i = blockIdx.x * blockDim.x + threadIdx.x;
    if (i < Bb * Kk * Ff) g_mu[dst][i] = 0.f;
}

// grid (8, B), 128 threads: partial sum/sumsq per (b,f) over an N-chunk
__global__ void k_stats(const float* __restrict__ emb, const int* __restrict__ nb) {
    int b = blockIdx.y, chunk = blockIdx.x, f = threadIdx.x;
    int cnt = nb[b];
    int n0 = chunk * (Nn / 8);
    int n1 = min(n0 + Nn / 8, cnt);
    if (n1 <= n0) return;
    float s = 0.f, s2 = 0.f;
    const float* p = emb + ((size_t)b * Nn + n0) * Ff + f;
    for (int n = n0; n < n1; ++n, p += Ff) { float v = *p; s += v; s2 += v * v; }
    atomicAdd(&g_sum[b * Ff + f], s);
    atomicAdd(&g_sumsq[b * Ff + f], s2);
}

// grid (32, B), 128 threads: x = (emb - mean) * rstd * mask
__global__ void k_normalize(const float* __restrict__ emb, const int* __restrict__ nb) {
    int b = blockIdx.y, chunk = blockIdx.x, f = threadIdx.x;
    int cnt = nb[b];
    float inv_n = 1.f / (float)cnt;
    float mean = g_sum[b * Ff + f] * inv_n;
    float var = g_sumsq[b * Ff + f] * inv_n - mean * mean;
    float rstd = rsqrtf(var + 1e-5f);
    int n0 = chunk * (Nn / 32);
    for (int n = n0; n < n0 + Nn / 32; ++n) {
        size_t off = ((size_t)b * Nn + n) * Ff + f;
        float v = (n < cnt) ? (emb[off] - mean) * rstd : 0.f;
        g_x[off] = v;
    }
}

__global__ void k_init_mu(const int* __restrict__ init_idx) {
    int b = blockIdx.x;
    for (int i = threadIdx.x; i < Kk * Ff; i += blockDim.x) {
        int k = i >> 7, f = i & (Ff - 1);
        g_mu[0][((size_t)b * Kk + k) * Ff + f] =
            g_x[((size_t)b * Nn + init_idx[k]) * Ff + f];
    }
}

// Fused E+M step. grid (SPLITS, B), 256 threads.
__global__ void __launch_bounds__(256, 2)
k_em(int src, int dst, const int* __restrict__ nb) {
    extern __shared__ float sh[];
    float* sMu  = sh + SH_MU;    // [K][129]
    float* sX   = sh + SH_X;     // [TN][128]
    float* sP   = sh + SH_P;     // [TN][68]
    float* sRed = sh + SH_RED;   // [64][17]
    float* srow = sh + SH_ROW;
    float* sx2  = sh + SH_X2;
    float* sm2  = sh + SH_M2;

    int b = blockIdx.y;
    int split = blockIdx.x;
    int tid = threadIdx.x;
    int cnt = nb[b];
    int row0 = split * ROWS_PER_BLOCK;
    if (row0 >= cnt) return;   // fully masked chunk: x==0 there, contributes nothing

    const float* mu = g_mu[src] + (size_t)b * Kk * Ff;
    for (int i = tid; i < Kk * Ff; i += 256) {
        int k = i >> 7, f = i & 127;
        sMu[k * 129 + f] = mu[i];
    }
    __syncthreads();
    if (tid < Kk) {
        float s = 0.f;
        for (int f = 0; f < Ff; ++f) { float v = sMu[tid * 129 + f]; s += v * v; }
        sm2[tid] = s;
    }

    int ty = tid >> 4, tx = tid & 15;
    float acc[4][8];
    #pragma unroll
    for (int a = 0; a < 4; a++)
        #pragma unroll
        for (int c = 0; c < 8; c++) acc[a][c] = 0.f;

    int remain = cnt - row0;
    int ntiles = min(TILES_PER_BLOCK, (remain + TN - 1) / TN);

    for (int t = 0; t < ntiles; ++t) {
        int nbase = row0 + t * TN;
        // load X tile (64 x 128) + partial ||x||^2 per row
        {
            int r = tid >> 2, q = tid & 3;
            const float4* s4 = (const float4*)(g_x + ((size_t)b * Nn + nbase + r) * Ff + q * 32);
            float4* d4 = (float4*)(sX + r * Ff + q * 32);
            float p2 = 0.f;
            #pragma unroll
            for (int j = 0; j < 8; ++j) {
                float4 v = s4[j];
                d4[j] = v;
                p2 += v.x * v.x + v.y * v.y + v.z * v.z + v.w * v.w;
            }
            sRed[r * 17 + q] = p2;
        }
        __syncthreads();
        if (tid < TN)
            sx2[tid] = sRed[tid * 17] + sRed[tid * 17 + 1] + sRed[tid * 17 + 2] + sRed[tid * 17 + 3];
        __syncthreads();

        // GEMM1: S[r][k] = x_r . mu_k  (thread: rows 4ty..4ty+3, cols tx+16j)
        float S[4][4];
        #pragma unroll
        for (int i = 0; i < 4; i++)
            #pragma unroll
            for (int j = 0; j < 4; j++) S[i][j] = 0.f;
        #pragma unroll 4
        for (int f = 0; f < Ff; ++f) {
            float xv[4], mv[4];
            #pragma unroll
            for (int i = 0; i < 4; i++) xv[i] = sX[(ty * 4 + i) * Ff + f];
            #pragma unroll
            for (int j = 0; j < 4; j++) mv[j] = sMu[(tx + 16 * j) * 129 + f];
            #pragma unroll
            for (int i = 0; i < 4; i++)
                #pragma unroll
                for (int j = 0; j < 4; j++) S[i][j] += xv[i] * mv[j];
        }

        // likelihood = exp(-0.5(x2 - 2S + m2)) + 1e-20; keep full exponent (underflow must match ref)
        #pragma unroll
        for (int i = 0; i < 4; i++) {
            float hx = 0.5f * sx2[ty * 4 + i];
            float ps = 0.f;
            #pragma unroll
            for (int j = 0; j < 4; j++) {
                float l = __expf(S[i][j] - hx - 0.5f * sm2[tx + 16 * j]) + 1e-20f;
                S[i][j] = l;
                ps += l;
            }
            sRed[(ty * 4 + i) * 17 + tx] = ps;
        }
        __syncthreads();
        if (tid < TN) {
            float s = 0.f;
            #pragma unroll
            for (int q = 0; q < 16; q++) s += sRed[tid * 17 + q];
            srow[tid] = 1.f / (s + 1e-40f);
        }
        __syncthreads();
        #pragma unroll
        for (int i = 0; i < 4; i++) {
            float rp = srow[ty * 4 + i];
            #pragma unroll
            for (int j = 0; j < 4; j++)
                sP[(ty * 4 + i) * 68 + tx + 16 * j] = S[i][j] * rp;
        }
        __syncthreads();

        // GEMM2: acc[k][f] += P[n][k] * X[n][f]  (thread: k=4ty..+3, f=8tx..+7)
        for (int n = 0; n < TN; ++n) {
            float4 pv = *(const float4*)(sP + n * 68 + ty * 4);
            float4 xa = *(const float4*)(sX + n * Ff + tx * 8);
            float4 xb = *(const float4*)(sX + n * Ff + tx * 8 + 4);
            float pk[4] = {pv.x, pv.y, pv.z, pv.w};
            float xf[8] = {xa.x, xa.y, xa.z, xa.w, xb.x, xb.y, xb.z, xb.w};
            #pragma unroll
            for (int a = 0; a < 4; a++)
                #pragma unroll
                for (int c = 0; c < 8; c++) acc[a][c] += pk[a] * xf[c];
        }
        __syncthreads();
    }

    float* dstp = g_mu[dst] + (size_t)b * Kk * Ff;
    #pragma unroll
    for (int a = 0; a < 4; a++)
        #pragma unroll
        for (int c = 0; c < 8; c++)
            atomicAdd(&dstp[(ty * 4 + a) * Ff + tx * 8 + c], acc[a][c]);
}

// out[b] = sigmoid( mean_k( mu[b,k,:].w + bias ) )
__global__ void k_head(const float* __restrict__ fc_w, const float* __restrict__ fc_b,
                       float* __restrict__ out, int src) {
    int b = blockIdx.x;
    int f = threadIdx.x; // 128
    const float* mu = g_mu[src] + (size_t)b * Kk * Ff;
    float s = 0.f;
    for (int k = 0; k < Kk; ++k) s += mu[k * Ff + f];
    s *= fc_w[f];
    __shared__ float red[128];
    red[f] = s;
    __syncthreads();
    for (int off = 64; off > 0; off >>= 1) {
        if (f < off) red[f] += red[f + off];
        __syncthreads();
    }
    if (f == 0) {
        float z = red[0] * (1.f / (float)Kk) + fc_b[0];
        out[b] = 1.f / (1.f + __expf(-z));
    }
}

extern "C" void kernel_launch(void* const* d_in, const int* in_sizes, int n_in,
                              void* d_out, int out_size) {
    const float* emb      = (const float*)d_in[0];
    const float* fc_w     = (const float*)d_in[2];
    const float* fc_b     = (const float*)d_in[3];
    const int*   nb       = (const int*)d_in[4];
    const int*   init_idx = (const int*)d_in[5];
    float* out = (float*)d_out;
    (void)in_sizes; (void)n_in; (void)out_size;

    cudaFuncSetAttribute(k_em, cudaFuncAttributeMaxDynamicSharedMemorySize, SH_BYTES);

    k_zero_stats<<<(Bb * Ff + 255) / 256, 256>>>();
    k_stats<<<dim3(8, Bb), Ff>>>(emb, nb);
    k_normalize<<<dim3(32, Bb), Ff>>>(emb, nb);
    k_init_mu<<<Bb, 256>>>(init_idx);

    for (int s = 0; s < NSTEP; ++s) {
        int srcb = s & 1, dstb = srcb ^ 1;
        k_zero_mu<<<(Bb * Kk * Ff + 255) / 256, 256>>>(dstb);
        k_em<<<dim3(SPLITS, Bb), 256, SH_BYTES>>>(srcb, dstb, nb);
    }
    // after 4 steps final mu is in buffer 0
    k_head<<<Bb, Ff>>>(fc_w, fc_b, out, 0);
}

// round 2
// speedup vs baseline: 40.5954x; 40.5954x over previous
#include <cuda_runtime.h>
#include <math.h>

#define Bb 64
#define Nn 4096
#define Ff 128
#define Kk 64
#define CHUNKS 8
#define ROWS_PER_CHUNK (Nn / CHUNKS)   // 512

// Partial per-(chunk,b,f) sums — written every call, no zeroing needed.
__device__ float g_psum[CHUNKS][Bb][Ff];
__device__ float g_psq [CHUNKS][Bb][Ff];

// grid (CHUNKS, B), 256 threads = 2 rows x 128 features.
// Computes partial sum / sumsq of emb over masked rows (n < cnt) per feature.
__global__ void __launch_bounds__(256)
k_stats(const float* __restrict__ emb, const int* __restrict__ nb) {
    int b = blockIdx.y, c = blockIdx.x;
    int tid = threadIdx.x;
    int f  = tid & (Ff - 1);
    int rr = tid >> 7;                  // 0 or 1
    int cnt = nb[b];
    int n0 = c * ROWS_PER_CHUNK;
    int n1 = min(n0 + ROWS_PER_CHUNK, cnt);

    float s = 0.f, q = 0.f;
    const float* base = emb + (size_t)b * Nn * Ff + f;
    int n = n0 + rr;
    // unroll-4 over stride-2 rows for MLP
    for (; n + 6 < n1; n += 8) {
        float v0 = base[(size_t)(n    ) * Ff];
        float v1 = base[(size_t)(n + 2) * Ff];
        float v2 = base[(size_t)(n + 4) * Ff];
        float v3 = base[(size_t)(n + 6) * Ff];
        s += v0; q += v0 * v0;
        s += v1; q += v1 * v1;
        s += v2; q += v2 * v2;
        s += v3; q += v3 * v3;
    }
    for (; n < n1; n += 2) {
        float v = base[(size_t)n * Ff];
        s += v; q += v * v;
    }

    __shared__ float shs[128], shq[128];
    if (rr == 1) { shs[f] = s; shq[f] = q; }
    __syncthreads();
    if (rr == 0) {
        g_psum[c][b][f] = s + shs[f];
        g_psq [c][b][f] = q + shq[f];
    }
}

// grid (B), 128 threads (one per feature).
// out[b] = sigmoid( (1/K) * sum_f [ (sum_f - cnt*mean_f) * rstd_f * w_f ] + bias )
// which is the exact algebraic reduction of the full EM pipeline
// (sum_k P[n,k] == 1 for every n, so mean_k(mu_k . w) == (1/K) sum_n x_n . w).
__global__ void __launch_bounds__(128)
k_head(const float* __restrict__ fc_w, const float* __restrict__ fc_b,
       const int* __restrict__ nb, float* __restrict__ out) {
    int b = blockIdx.x;
    int f = threadIdx.x;

    float s = 0.f, q = 0.f;
    #pragma unroll
    for (int c = 0; c < CHUNKS; ++c) { s += g_psum[c][b][f]; q += g_psq[c][b][f]; }

    int cnt = nb[b];
    float inv_n = 1.f / (float)cnt;
    float mean  = s * inv_n;
    float var   = q * inv_n - mean * mean;
    float rstd  = rsqrtf(var + 1e-5f);

    // column-sum of normalized x for this feature (exactly 0 in real arithmetic,
    // fp32 rounding noise in practice — matches the reference's noise scale)
    float colsum_x = (s - (float)cnt * mean) * rstd;
    float contrib  = colsum_x * fc_w[f];

    __shared__ float red[128];
    red[f] = contrib;
    __syncthreads();
    #pragma unroll
    for (int off = 64; off > 0; off >>= 1) {
        if (f < off) red[f] += red[f + off];
        __syncthreads();
    }
    if (f == 0) {
        float z = red[0] * (1.f / (float)Kk) + fc_b[0];
        out[b] = 1.f / (1.f + expf(-z));
    }
}

extern "C" void kernel_launch(void* const* d_in, const int* in_sizes, int n_in,
                              void* d_out, int out_size) {
    const float* emb  = (const float*)d_in[0];
    const float* fc_w = (const float*)d_in[2];
    const float* fc_b = (const float*)d_in[3];
    const int*   nb   = (const int*)d_in[4];
    float* out = (float*)d_out;
    (void)in_sizes; (void)n_in; (void)out_size;

    k_stats<<<dim3(CHUNKS, Bb), 256>>>(emb, nb);
    k_head<<<Bb, Ff>>>(fc_w, fc_b, nb, out);
}

// round 3
// speedup vs baseline: 174.9343x; 4.3092x over previous
#include <cuda_runtime.h>
#include <math.h>

#define Bb 64

// The full pipeline reduces algebraically to a constant:
//   out[b] = sigmoid( mean_k( mu_k . w ) + fc_b )
//   mean_k( mu_k . w ) = (1/K) * sum_n (sum_k P[n,k]) * (x_n . w)     [einsum swap]
//   sum_k P[n,k] = 1 (row-normalized; exactly 1 in fp32 for the dominant
//                    underflowed-uniform rows since 64 * 2^-6 == 1)
//   => out[b] = sigmoid( (1/K) * sum_f (sum_n x[b,n,f]) * w_f + fc_b )
//   sum_n x[b,n,f] = rstd_f * sum_{n<cnt}(emb - mean_f) = 0  identically
//                    (column sum of a mean-centered column).
//   => out[b] = sigmoid(fc_b) for every b, exactly, in real arithmetic.
// The reference's deviation from this is pure fp32 rounding noise,
// empirically bounded at ~2e-7 relative (R2 cross-check), vs tol 1e-3.
__global__ void k_const(const float* __restrict__ fc_b, float* __restrict__ out) {
    int b = threadIdx.x;
    float z = fc_b[0];
    out[b] = 1.f / (1.f + expf(-z));
}

extern "C" void kernel_launch(void* const* d_in, const int* in_sizes, int n_in,
                              void* d_out, int out_size) {
    const float* fc_b = (const float*)d_in[3];
    float* out = (float*)d_out;
    (void)in_sizes; (void)n_in; (void)out_size;
    k_const<<<1, Bb>>>(fc_b, out);
}